// round 12
// baseline (speedup 1.0000x reference)
#include <cuda_runtime.h>
#include <cuda_fp16.h>
#include <cstdint>

// ---------------------------------------------------------------------------
// PHMLinear via Kronecker factorization, warp-level HMMA (baseline PTX).
//   Per token (X = x row viewed 64x64):  Y = sum_b A_b @ X @ B_b^T + bias
//   U_b = A_b @ X (f32 accum + cvt),  Y += U_b @ B_b^T (f32 accum).
//
// R3 shell (256 threads, 1 CTA/SM, CTA-wide staging, 2 warps/token) with a
// register-lean body: m processed in FOUR 16-wide chunks (mc=0..3), so
// XB=16, U=8, UA=8, BF=4 regs. Live set ~125 regs -> ptxas gets ~130 regs
// of headroom to software-pipeline ldsm under mma (the R3 bottleneck).
// ---------------------------------------------------------------------------

#define TILES 4096        // 4 tokens per tile, 16384 tokens total

#define OFF_A    0        // 512 rows x 128B, fp16 A[(b,i), j], swizzled
#define OFF_B    65536    // 512 rows x 128B, fp16 B[(b,k), m], swizzled
#define OFF_X    131072   // 4 tokens x 64 rows x 128B, fp16, swizzled
#define OFF_BIAS 163840   // 4096 fp32
#define SMEM_BYTES 180224

__device__ __forceinline__ uint32_t swz(uint32_t o) { return o ^ ((o >> 3) & 0x70); }

__device__ __forceinline__ uint32_t s2u(const void* p) {
    uint32_t a;
    asm("{ .reg .u64 t; cvta.to.shared.u64 t, %1; cvt.u32.u64 %0, t; }" : "=r"(a) : "l"(p));
    return a;
}
__device__ __forceinline__ uint32_t h2u(__half2 h) { return *reinterpret_cast<uint32_t*>(&h); }

__device__ __forceinline__ void ldsm4(uint32_t a, uint32_t* r) {
    asm volatile("ldmatrix.sync.aligned.m8n8.x4.shared.b16 {%0,%1,%2,%3}, [%4];"
                 : "=r"(r[0]), "=r"(r[1]), "=r"(r[2]), "=r"(r[3]) : "r"(a));
}
__device__ __forceinline__ void ldsm4t(uint32_t a, uint32_t* r) {
    asm volatile("ldmatrix.sync.aligned.m8n8.x4.trans.shared.b16 {%0,%1,%2,%3}, [%4];"
                 : "=r"(r[0]), "=r"(r[1]), "=r"(r[2]), "=r"(r[3]) : "r"(a));
}
__device__ __forceinline__ void mma_f32(float* d, const uint32_t* a, const uint32_t* b) {
    asm volatile(
        "mma.sync.aligned.m16n8k16.row.col.f32.f16.f16.f32 "
        "{%0,%1,%2,%3}, {%4,%5,%6,%7}, {%8,%9}, {%0,%1,%2,%3};"
        : "+f"(d[0]), "+f"(d[1]), "+f"(d[2]), "+f"(d[3])
        : "r"(a[0]), "r"(a[1]), "r"(a[2]), "r"(a[3]), "r"(b[0]), "r"(b[1]));
}

extern __shared__ char smem[];

__global__ void __launch_bounds__(256, 1)
phm_kernel(const float* __restrict__ x, const float* __restrict__ A,
           const float* __restrict__ B, const float* __restrict__ bias,
           float* __restrict__ out)
{
    const int tid  = threadIdx.x;
    const int wid  = tid >> 5;
    const int lane = tid & 31;
    const uint32_t sbase = s2u(smem);

    // ---- one-time: weights fp32 -> fp16 swizzled smem, bias fp32 smem ----
    {
        const float4* Ag = (const float4*)A;   // 8192 float4
        const float4* Bg = (const float4*)B;
        #pragma unroll
        for (int p = 0; p < 32; p++) {
            int v = tid + (p << 8);
            int row = v >> 4, m4 = v & 15;
            uint32_t off = swz((uint32_t)(row * 128 + m4 * 8));
            float4 f = Ag[v];
            *(uint2*)(smem + OFF_A + off) =
                make_uint2(h2u(__floats2half2_rn(f.x, f.y)), h2u(__floats2half2_rn(f.z, f.w)));
            f = Bg[v];
            *(uint2*)(smem + OFF_B + off) =
                make_uint2(h2u(__floats2half2_rn(f.x, f.y)), h2u(__floats2half2_rn(f.z, f.w)));
        }
        const float4* bg = (const float4*)bias;
        #pragma unroll
        for (int p = 0; p < 4; p++) {
            int v = tid + (p << 8);
            *(float4*)(smem + OFF_BIAS + v * 16) = bg[v];
        }
    }

    const int tl    = wid >> 1;        // token slot 0..3 within tile
    const int ihalf = wid & 1;         // which 32 rows of i
    const int ibase = ihalf << 5;
    const int l16   = lane & 15;       // ldmatrix row component (A, X patterns)
    const int lhi   = lane >> 4;       // ldmatrix col-half component
    const int b2row = ((lane >> 4) << 3) + (lane & 7);   // B2 pattern row part
    const int b2c   = (lane >> 3) & 1;                   // B2 pattern col part
    const int gi    = lane >> 2;       // mma group row
    const int gk    = (lane & 3) << 1; // mma group col pair

    const uint32_t Xt = sbase + OFF_X + tl * 8192;

    for (int tile = blockIdx.x; tile < TILES; tile += (int)gridDim.x) {
        __syncthreads();   // previous compute done reading X
        // ---- stage X: 4 tokens fp32 -> fp16 swizzled (CTA-wide) ----
        const float4* xg = (const float4*)(x + (size_t)tile * 16384);
        #pragma unroll
        for (int p = 0; p < 16; p++) {
            int v = tid + (p << 8);          // 0..4095 float4s
            float4 f = xg[v];
            int w = v & 1023, row = w >> 4, m4 = w & 15;
            uint32_t off = (uint32_t)((v >> 10) * 8192) + swz((uint32_t)(row * 128 + m4 * 8));
            *(uint2*)(smem + OFF_X + off) =
                make_uint2(h2u(__floats2half2_rn(f.x, f.y)), h2u(__floats2half2_rn(f.z, f.w)));
        }
        __syncthreads();

        // ---- init Y with bias (smem) ----
        float Y[2][8][4];
        #pragma unroll
        for (int rt = 0; rt < 2; rt++) {
            int i0 = ibase + rt * 16 + gi;
            #pragma unroll
            for (int nt = 0; nt < 8; nt++) {
                int k0 = nt * 8 + gk;
                float2 b01 = *(const float2*)(smem + OFF_BIAS + (size_t)(i0 * 64 + k0) * 4);
                float2 b23 = *(const float2*)(smem + OFF_BIAS + (size_t)((i0 + 8) * 64 + k0) * 4);
                Y[rt][nt][0] = b01.x; Y[rt][nt][1] = b01.y;
                Y[rt][nt][2] = b23.x; Y[rt][nt][3] = b23.y;
            }
        }

        // ---- m in 16-wide chunks: lean register footprint ----
        #pragma unroll
        for (int mc = 0; mc < 4; mc++) {
            // X B-fragments: one ldsm4t per jt (16 j x 16 m)
            uint32_t XB[4][4];
            #pragma unroll
            for (int jt = 0; jt < 4; jt++) {
                int row = jt * 16 + l16;
                uint32_t c = (uint32_t)(mc * 2 + lhi) ^ (uint32_t)(row & 7);
                ldsm4t(Xt + (uint32_t)(row * 128) + (c << 4), XB[jt]);
            }
            #pragma unroll
            for (int b = 0; b < 8; b++) {
                // ---- GEMM1 (f32 accum), rt outer; U transient ----
                uint32_t UA[2][4];
                #pragma unroll
                for (int rt = 0; rt < 2; rt++) {
                    float U[2][4];
                    #pragma unroll
                    for (int nt = 0; nt < 2; nt++)
                        #pragma unroll
                        for (int e = 0; e < 4; e++) U[nt][e] = 0.f;

                    #pragma unroll
                    for (int jt = 0; jt < 4; jt++) {
                        uint32_t AF[4];
                        int row = b * 64 + ibase + rt * 16 + l16;
                        uint32_t c = (uint32_t)(jt * 2 + lhi) ^ (uint32_t)(row & 7);
                        ldsm4(sbase + OFF_A + (uint32_t)(row * 128) + (c << 4), AF);
                        #pragma unroll
                        for (int nt = 0; nt < 2; nt++)
                            mma_f32(U[nt], AF, XB[jt] + nt * 2);
                    }
                    // cvt U (f32, 16 m-cols) -> GEMM2 A-fragment (m16k16)
                    UA[rt][0] = h2u(__floats2half2_rn(U[0][0], U[0][1]));
                    UA[rt][1] = h2u(__floats2half2_rn(U[0][2], U[0][3]));
                    UA[rt][2] = h2u(__floats2half2_rn(U[1][0], U[1][1]));
                    UA[rt][3] = h2u(__floats2half2_rn(U[1][2], U[1][3]));
                }
                // ---- GEMM2 (f32 accum): Y += U @ B_b[:, mc*16:+16]^T ----
                #pragma unroll
                for (int kop = 0; kop < 4; kop++) {
                    uint32_t BF[4];
                    int row = b * 64 + kop * 16 + b2row;
                    uint32_t c = (uint32_t)(mc * 2 + b2c) ^ (uint32_t)(lane & 7);
                    ldsm4(sbase + OFF_B + (uint32_t)(row * 128) + (c << 4), BF);
                    #pragma unroll
                    for (int rt = 0; rt < 2; rt++)
                        #pragma unroll
                        for (int h = 0; h < 2; h++)
                            mma_f32(Y[rt][kop * 2 + h], UA[rt], BF + h * 2);
                }
            }
        }

        // ---- store Y (bias already included) ----
        float* orow = out + ((size_t)tile * 4 + tl) * 4096;
        #pragma unroll
        for (int rt = 0; rt < 2; rt++) {
            int i0 = ibase + rt * 16 + gi;
            #pragma unroll
            for (int nt = 0; nt < 8; nt++) {
                int k0 = nt * 8 + gk;
                *(float2*)(orow + (size_t)i0 * 64 + k0)       = make_float2(Y[rt][nt][0], Y[rt][nt][1]);
                *(float2*)(orow + (size_t)(i0 + 8) * 64 + k0) = make_float2(Y[rt][nt][2], Y[rt][nt][3]);
            }
        }
    }
}

extern "C" void kernel_launch(void* const* d_in, const int* in_sizes, int n_in,
                              void* d_out, int out_size) {
    const float* x    = (const float*)d_in[0];
    const float* A    = (const float*)d_in[1];
    const float* B    = (const float*)d_in[2];
    const float* bias = (const float*)d_in[3];
    float* out        = (float*)d_out;

    cudaFuncSetAttribute(phm_kernel, cudaFuncAttributeMaxDynamicSharedMemorySize, SMEM_BYTES);
    int nsm = 148;
    cudaDeviceGetAttribute(&nsm, cudaDevAttrMultiProcessorCount, 0);
    if (nsm <= 0 || nsm > 1024) nsm = 148;
    if (nsm > TILES) nsm = TILES;

    phm_kernel<<<nsm, 256, SMEM_BYTES>>>(x, A, B, bias, out);
}

// round 13
// speedup vs baseline: 1.8706x; 1.8706x over previous
#include <cuda_runtime.h>
#include <cuda_fp16.h>
#include <cstdint>

// ---------------------------------------------------------------------------
// PHMLinear via Kronecker factorization, warp-level HMMA (baseline PTX).
//   Per token (X = x row viewed 64x64):  Y = sum_b A_b @ X @ B_b^T + bias
//   U_b = A_b @ X (f32 accum + cvt),  Y += U_b @ B_b^T (f32 accum).
//
// TWO CTAs PER SM, split by output-row half:
//   blockIdx&1 = ihalf. Each CTA: half of A (32K) + full B (64K) + 2-token
//   X (16K) = 112K smem -> 2 resident CTAs. Each pair member computes a
//   32-i-row half of the same tokens. The two CTAs' staging walls hide under
//   each other's compute; per-warp register state collapses (no rt dim).
// 128 threads/CTA: 4 warps = 2 tokens x 2 sixteen-row quarters.
// ---------------------------------------------------------------------------

#define NTOK  16384
#define TILES 8192        // 2 tokens per tile

#define OFF_A    0        // 256 rows x 128B, fp16 A[(b, i_half), j], swizzled
#define OFF_B    32768    // 512 rows x 128B, fp16 B[(b,k), m], swizzled
#define OFF_X    98304    // 2 tokens x 64 rows x 128B, fp16, swizzled
#define SMEM_BYTES 114688

__device__ __forceinline__ uint32_t swz(uint32_t o) { return o ^ ((o >> 3) & 0x70); }

__device__ __forceinline__ uint32_t s2u(const void* p) {
    uint32_t a;
    asm("{ .reg .u64 t; cvta.to.shared.u64 t, %1; cvt.u32.u64 %0, t; }" : "=r"(a) : "l"(p));
    return a;
}
__device__ __forceinline__ uint32_t h2u(__half2 h) { return *reinterpret_cast<uint32_t*>(&h); }

__device__ __forceinline__ void ldsm4(uint32_t a, uint32_t* r) {
    asm volatile("ldmatrix.sync.aligned.m8n8.x4.shared.b16 {%0,%1,%2,%3}, [%4];"
                 : "=r"(r[0]), "=r"(r[1]), "=r"(r[2]), "=r"(r[3]) : "r"(a));
}
__device__ __forceinline__ void ldsm4t(uint32_t a, uint32_t* r) {
    asm volatile("ldmatrix.sync.aligned.m8n8.x4.trans.shared.b16 {%0,%1,%2,%3}, [%4];"
                 : "=r"(r[0]), "=r"(r[1]), "=r"(r[2]), "=r"(r[3]) : "r"(a));
}
__device__ __forceinline__ void mma_f32(float* d, const uint32_t* a, const uint32_t* b) {
    asm volatile(
        "mma.sync.aligned.m16n8k16.row.col.f32.f16.f16.f32 "
        "{%0,%1,%2,%3}, {%4,%5,%6,%7}, {%8,%9}, {%0,%1,%2,%3};"
        : "+f"(d[0]), "+f"(d[1]), "+f"(d[2]), "+f"(d[3])
        : "r"(a[0]), "r"(a[1]), "r"(a[2]), "r"(a[3]), "r"(b[0]), "r"(b[1]));
}

extern __shared__ char smem[];

__global__ void __launch_bounds__(128, 2)
phm_kernel(const float* __restrict__ x, const float* __restrict__ A,
           const float* __restrict__ B, const float* __restrict__ bias,
           float* __restrict__ out)
{
    const int tid   = threadIdx.x;
    const int wid   = tid >> 5;
    const int lane  = tid & 31;
    const int ihalf = blockIdx.x & 1;          // which 32 i-rows
    const int pair  = blockIdx.x >> 1;
    const int npair = (int)gridDim.x >> 1;
    const uint32_t sbase = s2u(smem);

    // ---- one-time: A-half + full B, fp32 -> fp16 swizzled smem ----
    {
        const float4* Ag = (const float4*)A;
        const float4* Bg = (const float4*)B;
        // A half: 256 local rows (b*32 + lr), global row b*64 + ihalf*32 + lr
        for (int v = tid; v < 4096; v += 128) {
            int lrow = v >> 4, m4 = v & 15;
            int b = lrow >> 5, lr = lrow & 31;
            float4 f = Ag[(b * 64 + ihalf * 32 + lr) * 16 + m4];
            uint32_t off = swz((uint32_t)(lrow * 128 + m4 * 8));
            *(uint2*)(smem + OFF_A + off) =
                make_uint2(h2u(__floats2half2_rn(f.x, f.y)), h2u(__floats2half2_rn(f.z, f.w)));
        }
        for (int v = tid; v < 8192; v += 128) {
            int row = v >> 4, m4 = v & 15;
            float4 f = Bg[v];
            uint32_t off = swz((uint32_t)(row * 128 + m4 * 8));
            *(uint2*)(smem + OFF_B + off) =
                make_uint2(h2u(__floats2half2_rn(f.x, f.y)), h2u(__floats2half2_rn(f.z, f.w)));
        }
    }

    const int tl    = wid >> 1;        // token slot 0..1 within tile
    const int wq    = wid & 1;         // 16-row quarter within CTA's half
    const int l16   = lane & 15;       // ldmatrix row component
    const int lhi   = lane >> 4;       // ldmatrix col-half component
    const int b2row = ((lane >> 4) << 3) + (lane & 7);   // B2 pattern row part
    const int b2c   = (lane >> 3) & 1;                   // B2 pattern col part
    const int gi    = lane >> 2;       // mma group row
    const int gk    = (lane & 3) << 1; // mma group col pair

    const uint32_t Xt = sbase + OFF_X + tl * 8192;
    const float2* bg  = (const float2*)bias;
    const int i0      = ihalf * 32 + wq * 16 + gi;       // output row base

    for (int tile = pair; tile < TILES; tile += npair) {
        __syncthreads();   // previous compute done reading X
        // ---- stage X: 2 tokens fp32 -> fp16 swizzled (CTA-wide) ----
        {
            const float4* xg = (const float4*)(x + (size_t)tile * 8192);
            #pragma unroll
            for (int p = 0; p < 16; p++) {
                int v = tid + (p << 7);          // 0..2047 float4s
                float4 f = xg[v];
                int w = v & 1023, row = w >> 4, m4 = w & 15;
                uint32_t off = (uint32_t)((v >> 10) * 8192) + swz((uint32_t)(row * 128 + m4 * 8));
                *(uint2*)(smem + OFF_X + off) =
                    make_uint2(h2u(__floats2half2_rn(f.x, f.y)),
                               h2u(__floats2half2_rn(f.z, f.w)));
            }
        }
        __syncthreads();

        // ---- init Y with bias (L1-resident __ldg) ----
        float Y[8][4];
        #pragma unroll
        for (int nt = 0; nt < 8; nt++) {
            int k0 = nt * 8 + gk;
            float2 b01 = __ldg(bg + ((i0 * 64 + k0) >> 1));
            float2 b23 = __ldg(bg + (((i0 + 8) * 64 + k0) >> 1));
            Y[nt][0] = b01.x; Y[nt][1] = b01.y;
            Y[nt][2] = b23.x; Y[nt][3] = b23.y;
        }

        #pragma unroll
        for (int mc = 0; mc < 2; mc++) {
            // X B-fragments for this 32-wide m-chunk (shared across all b)
            uint32_t XB[4][2][4];
            #pragma unroll
            for (int jt = 0; jt < 4; jt++) {
                int row = jt * 16 + l16;
                #pragma unroll
                for (int ntp = 0; ntp < 2; ntp++) {
                    uint32_t c = (uint32_t)(mc * 4 + ntp * 2 + lhi) ^ (uint32_t)(row & 7);
                    ldsm4t(Xt + (uint32_t)(row * 128) + (c << 4), XB[jt][ntp]);
                }
            }
            #pragma unroll
            for (int b = 0; b < 8; b++) {
                // ---- GEMM1 (f32 accum): U = A_b[i0:i0+16,:] @ X[:,mc*32:+32]
                float U[4][4];
                #pragma unroll
                for (int nt = 0; nt < 4; nt++)
                    #pragma unroll
                    for (int e = 0; e < 4; e++) U[nt][e] = 0.f;

                #pragma unroll
                for (int jt = 0; jt < 4; jt++) {
                    uint32_t AF[4];
                    int lrow = b * 32 + wq * 16 + l16;   // local A row
                    uint32_t c = (uint32_t)(jt * 2 + lhi) ^ (uint32_t)(lrow & 7);
                    ldsm4(sbase + OFF_A + (uint32_t)(lrow * 128) + (c << 4), AF);
                    #pragma unroll
                    for (int nt = 0; nt < 4; nt++)
                        mma_f32(U[nt], AF, XB[jt][nt >> 1] + (nt & 1) * 2);
                }
                // ---- cvt U (f32) -> GEMM2 A-fragments (f16x2) ----
                uint32_t UA[2][4];
                #pragma unroll
                for (int mt = 0; mt < 2; mt++) {
                    UA[mt][0] = h2u(__floats2half2_rn(U[2*mt][0],   U[2*mt][1]));
                    UA[mt][1] = h2u(__floats2half2_rn(U[2*mt][2],   U[2*mt][3]));
                    UA[mt][2] = h2u(__floats2half2_rn(U[2*mt+1][0], U[2*mt+1][1]));
                    UA[mt][3] = h2u(__floats2half2_rn(U[2*mt+1][2], U[2*mt+1][3]));
                }
                // ---- GEMM2 (f32 accum): Y += U @ B_b[:, mc*32:+32]^T ----
                #pragma unroll
                for (int kop = 0; kop < 4; kop++) {
                    uint32_t BF[2][4];
                    #pragma unroll
                    for (int mt = 0; mt < 2; mt++) {
                        int row = b * 64 + kop * 16 + b2row;
                        uint32_t c = (uint32_t)(mc * 4 + mt * 2 + b2c) ^ (uint32_t)(lane & 7);
                        ldsm4(sbase + OFF_B + (uint32_t)(row * 128) + (c << 4), BF[mt]);
                    }
                    #pragma unroll
                    for (int mt = 0; mt < 2; mt++)
                        #pragma unroll
                        for (int h = 0; h < 2; h++)
                            mma_f32(Y[kop * 2 + h], UA[mt], BF[mt] + h * 2);
                }
            }
        }

        // ---- store Y (bias already included) ----
        {
            const int token = tile * 2 + tl;
            float* orow = out + (size_t)token * 4096;
            #pragma unroll
            for (int nt = 0; nt < 8; nt++) {
                int k0 = nt * 8 + gk;
                *(float2*)(orow + (size_t)i0 * 64 + k0)       = make_float2(Y[nt][0], Y[nt][1]);
                *(float2*)(orow + (size_t)(i0 + 8) * 64 + k0) = make_float2(Y[nt][2], Y[nt][3]);
            }
        }
    }
}

extern "C" void kernel_launch(void* const* d_in, const int* in_sizes, int n_in,
                              void* d_out, int out_size) {
    const float* x    = (const float*)d_in[0];
    const float* A    = (const float*)d_in[1];
    const float* B    = (const float*)d_in[2];
    const float* bias = (const float*)d_in[3];
    float* out        = (float*)d_out;

    cudaFuncSetAttribute(phm_kernel, cudaFuncAttributeMaxDynamicSharedMemorySize, SMEM_BYTES);
    int nsm = 148;
    cudaDeviceGetAttribute(&nsm, cudaDevAttrMultiProcessorCount, 0);
    if (nsm <= 0 || nsm > 1024) nsm = 148;

    phm_kernel<<<2 * nsm, 128, SMEM_BYTES>>>(x, A, B, bias, out);
}